// round 2
// baseline (speedup 1.0000x reference)
#include <cuda_runtime.h>

#define B_ 4
#define S_ 4096
#define NT (B_*S_)            // 16384 tokens
#define NSPLIT 4
#define KCHUNK (S_/NSPLIT)    // 1024 keys per block
#define QPB 128               // queries (=threads) per block

// Scratch (allocation-free: __device__ globals)
__device__ float4 g_P[NT];          // packed p: (p0_h0, p0_h1, p1_h0, p1_h1), includes log2e/sqrt(D) and rmsnorm
__device__ float2 g_NM[NT];         // (-M_h0, -M_h1) analytic score upper bounds (exp2 domain)
__device__ float4 g_K[NT];          // (k0,k0,k1,k1) duplicated for f32x2
__device__ float  g_SV[NT];         // s_v per token
__device__ float4 g_Part[NSPLIT][NT]; // partial (den0, den1, num0, num1)

// ---------------------------------------------------------------------------
// Kernel A: per-token projections + rmsnorm + rope, packed for the main loop
// ---------------------------------------------------------------------------
__global__ void prep_kernel(const float* __restrict__ x, const float* __restrict__ freqs,
                            const float* __restrict__ qkv, const float* __restrict__ vvec,
                            const float* __restrict__ qu,  const float* __restrict__ ku)
{
    int i = blockIdx.x * blockDim.x + threadIdx.x;
    if (i >= NT) return;
    int s = i & (S_ - 1);
    const float* xp = x + i * 5;
    float a = 0.f, av = 0.f;
#pragma unroll
    for (int j = 0; j < 5; j++) {
        float xv = xp[j];
        a  = fmaf(xv, qkv[j],  a);   // s_qk
        av = fmaf(xv, vvec[j], av);  // s_v
    }
    float c, sn;
    sincosf(freqs[s], &sn, &c);
    const float ALPHA = 1.0201415515301256f;   // log2(e) / sqrt(D=2)

    // key (KVH=1): rmsnorm(D=2) + rope
    float ku0 = ku[0], ku1 = ku[1];
    float mk   = 0.5f * (ku0*ku0 + ku1*ku1);
    float invk = rsqrtf(fmaf(a*a, mk, 1e-6f));
    float gk   = 16.f * a * invk;
    float kn0 = gk * ku0, kn1 = gk * ku1;
    float k0 = kn0*c - kn1*sn;
    float k1 = kn0*sn + kn1*c;
    g_K[i]  = make_float4(k0, k0, k1, k1);
    g_SV[i] = av;

    // queries, both heads
    float p0h[2], p1h[2], M[2];
#pragma unroll
    for (int h = 0; h < 2; h++) {
        float u0 = qu[2*h], u1 = qu[2*h+1];
        float mq  = 0.5f * (u0*u0 + u1*u1);
        float inv = rsqrtf(fmaf(a*a, mq, 1e-6f));
        float gq  = 16.f * a * inv;
        float qn0 = gq * u0, qn1 = gq * u1;
        float q0 = qn0*c - qn1*sn;
        float q1 = qn0*sn + qn1*c;
        p0h[h] = ALPHA * q0;
        p1h[h] = ALPHA * q1;
        // |k| <= 16*sqrt(2) exactly => analytic score upper bound (exp2 domain)
        M[h] = sqrtf(p0h[h]*p0h[h] + p1h[h]*p1h[h]) * 22.627417f;
    }
    g_P[i]  = make_float4(p0h[0], p0h[1], p1h[0], p1h[1]);
    g_NM[i] = make_float2(-M[0], -M[1]);
}

// ---------------------------------------------------------------------------
// Kernel B: softmax attention main loop. One thread = one query token, both
// heads packed via fma.rn.f32x2. Keys tile in shared, broadcast LDS.
// MUFU.EX2 is the intended binding pipe (2 EX2 per key-iter).
// ---------------------------------------------------------------------------
__global__ void __launch_bounds__(QPB) attn_kernel()
{
    __shared__ float4 sK[KCHUNK];
    __shared__ float  sV[KCHUNK];

    int b    = blockIdx.x;
    int part = blockIdx.y;
    int kbase = b * S_ + part * KCHUNK;
    for (int j = threadIdx.x; j < KCHUNK; j += QPB) {
        sK[j] = g_K[kbase + j];
        sV[j] = g_SV[kbase + j];
    }
    __syncthreads();

    int q = b * S_ + blockIdx.z * QPB + threadIdx.x;
    ulonglong2 P = *reinterpret_cast<const ulonglong2*>(&g_P[q]);
    unsigned long long pA = P.x;   // (p0_h0, p0_h1)
    unsigned long long pB = P.y;   // (p1_h0, p1_h1)
    unsigned long long nM = *reinterpret_cast<const unsigned long long*>(&g_NM[q]);

    float den0 = 0.f, den1 = 0.f, num0 = 0.f, num1 = 0.f;
    const ulonglong2* sKp = reinterpret_cast<const ulonglong2*>(sK);

#pragma unroll 8
    for (int j = 0; j < KCHUNK; j++) {
        ulonglong2 kk = sKp[j];            // .x = (k0,k0), .y = (k1,k1)
        float sv = sV[j];
        unsigned long long t0, s2;
        asm("fma.rn.f32x2 %0, %1, %2, %3;" : "=l"(t0) : "l"(pB), "l"(kk.y), "l"(nM));
        asm("fma.rn.f32x2 %0, %1, %2, %3;" : "=l"(s2) : "l"(pA), "l"(kk.x), "l"(t0));
        float2 sc = *reinterpret_cast<float2*>(&s2);   // (score_h0 - M0, score_h1 - M1), <= 0
        float e0, e1;
        asm("ex2.approx.ftz.f32 %0, %1;" : "=f"(e0) : "f"(sc.x));
        asm("ex2.approx.ftz.f32 %0, %1;" : "=f"(e1) : "f"(sc.y));
        den0 += e0;
        den1 += e1;
        num0 = fmaf(e0, sv, num0);
        num1 = fmaf(e1, sv, num1);
    }
    g_Part[part][q] = make_float4(den0, den1, num0, num1);
}

// ---------------------------------------------------------------------------
// Kernel C: combine split-K partials (plain add — M is analytic, shared
// across splits) + rank-1 epilogue.
// ---------------------------------------------------------------------------
__global__ void final_kernel(const float* __restrict__ ov, const float* __restrict__ uv,
                             const float* __restrict__ ou, float* __restrict__ out)
{
    int i = blockIdx.x * blockDim.x + threadIdx.x;
    if (i >= NT) return;
    float den0 = 0.f, den1 = 0.f, num0 = 0.f, num1 = 0.f;
#pragma unroll
    for (int p = 0; p < NSPLIT; p++) {
        float4 t = g_Part[p][i];
        den0 += t.x; den1 += t.y; num0 += t.z; num1 += t.w;
    }
    float r0 = num0 / den0;
    float r1 = num1 / den1;
    float C0 = uv[0]*ov[0] + uv[1]*ov[1];
    float C1 = uv[0]*ov[2] + uv[1]*ov[3];
    float so = r0*C0 + r1*C1;
    float* o = out + i * 5;
#pragma unroll
    for (int j = 0; j < 5; j++) o[j] = so * ou[j];
}

extern "C" void kernel_launch(void* const* d_in, const int* in_sizes, int n_in,
                              void* d_out, int out_size)
{
    const float* x     = (const float*)d_in[0];
    const float* freqs = (const float*)d_in[1];
    const float* qkv   = (const float*)d_in[2];
    const float* vv    = (const float*)d_in[3];
    const float* ov    = (const float*)d_in[4];
    const float* uv    = (const float*)d_in[5];
    const float* qu    = (const float*)d_in[6];
    const float* ku    = (const float*)d_in[7];
    const float* ou    = (const float*)d_in[8];

    prep_kernel<<<NT/256, 256>>>(x, freqs, qkv, vv, qu, ku);
    attn_kernel<<<dim3(B_, NSPLIT, S_/QPB), QPB>>>();
    final_kernel<<<NT/256, 256>>>(ov, uv, ou, (float*)d_out);
}

// round 4
// speedup vs baseline: 1.1447x; 1.1447x over previous
#include <cuda_runtime.h>

#define B_ 4
#define S_ 4096
#define NT (B_*S_)            // 16384 tokens
#define H_ 2
#define NBIN 128
#define NCHUNK (S_/32)        // 128 warp-chunks per batch
#define TWO_PI 6.283185307179586f
#define INVBIN (NBIN / TWO_PI)
#define WCUT 30.0f            // log2-domain pruning window

// ---- scratch (__device__ globals: allocation-free) ----
__device__ float4 g_QH[NT*H_];       // per (query,head): p0, p1, -M, psi
__device__ float2 g_Kvec[NT];        // key vector (k0,k1)
__device__ float  g_SV[NT];          // s_v per token
__device__ float  g_PSIK[NT];        // key angle in [0, 2pi)
__device__ float2 g_SK [B_*2*S_];    // angle-sorted keys, duplicated (wrap-free)
__device__ float  g_SSV[B_*2*S_];    // angle-sorted s_v, duplicated
__device__ int    g_binStart[B_][2*NBIN+1];
__device__ float  g_R[NT*H_];        // per (query,head) attention scalar num/den

// ---------------------------------------------------------------------------
// Kernel A: per-token projections + rmsnorm + rope; emit packed query records
// (p, -M, psi) per head and key records (kvec, sv, psi).
// ---------------------------------------------------------------------------
__global__ void __launch_bounds__(128) prep_kernel(
    const float* __restrict__ x, const float* __restrict__ freqs,
    const float* __restrict__ qkv, const float* __restrict__ vvec,
    const float* __restrict__ qu,  const float* __restrict__ ku)
{
    int i = blockIdx.x * blockDim.x + threadIdx.x;
    if (i >= NT) return;
    int s = i & (S_ - 1);
    const float* xp = x + i * 5;
    float a = 0.f, av = 0.f;
#pragma unroll
    for (int j = 0; j < 5; j++) {
        float xv = xp[j];
        a  = fmaf(xv, qkv[j],  a);   // s_qk
        av = fmaf(xv, vvec[j], av);  // s_v
    }
    float c, sn;
    sincosf(freqs[s], &sn, &c);
    const float ALPHA = 1.0201415515301256f;   // log2(e) / sqrt(D=2)

    // key (KVH=1): rmsnorm(D=2) + rope
    float ku0 = ku[0], ku1 = ku[1];
    float mk   = 0.5f * (ku0*ku0 + ku1*ku1);
    float invk = rsqrtf(fmaf(a*a, mk, 1e-6f));
    float gk   = 16.f * a * invk;
    float kn0 = gk * ku0, kn1 = gk * ku1;
    float k0 = kn0*c - kn1*sn;
    float k1 = kn0*sn + kn1*c;
    g_Kvec[i] = make_float2(k0, k1);
    g_SV[i]   = av;
    float psik = atan2f(k1, k0);
    if (psik < 0.f) psik += TWO_PI;
    g_PSIK[i] = psik;

    // queries, both heads
#pragma unroll
    for (int h = 0; h < 2; h++) {
        float u0 = qu[2*h], u1 = qu[2*h+1];
        float mq  = 0.5f * (u0*u0 + u1*u1);
        float inv = rsqrtf(fmaf(a*a, mq, 1e-6f));
        float gq  = 16.f * a * inv;
        float qn0 = gq * u0, qn1 = gq * u1;
        float q0 = qn0*c - qn1*sn;
        float q1 = qn0*sn + qn1*c;
        float p0 = ALPHA * q0, p1 = ALPHA * q1;
        // |k| < 16*sqrt(2) strictly => analytic score sup (log2 domain)
        float M = sqrtf(p0*p0 + p1*p1) * 22.627417f;
        float psi = atan2f(p1, p0);
        if (psi < 0.f) psi += TWO_PI;
        g_QH[i*2 + h] = make_float4(p0, p1, -M, psi);
    }
}

// ---------------------------------------------------------------------------
// Kernel B: deterministic stable counting sort of keys by angle bin.
// One block per batch. Stability: rank = (bin prefix) + (chunk prefix within
// bin) + (ballot rank within 32-key chunk) — no atomic-order dependence.
// ---------------------------------------------------------------------------
__global__ void __launch_bounds__(512) bin_kernel()
{
    __shared__ unsigned short cnt[NCHUNK][NBIN];   // 32KB: [chunk][bin]
    __shared__ unsigned char  s_bin[S_];
    __shared__ unsigned char  s_rank[S_];
    __shared__ int binTot[NBIN];
    __shared__ int binStart_s[NBIN+1];

    int b   = blockIdx.x;
    int tid = threadIdx.x;
    int lane = tid & 31, warp = tid >> 5;          // 16 warps

    for (int t = tid; t < NCHUNK*NBIN; t += 512)
        ((unsigned short*)cnt)[t] = 0;
    __syncthreads();

    // phase 1: per-chunk histograms + in-chunk stable ranks
    for (int c = warp; c < NCHUNK; c += 16) {
        int i = b*S_ + c*32 + lane;
        float psi = g_PSIK[i];
        int bin = (int)(psi * INVBIN);
        bin = min(max(bin, 0), NBIN-1);
        unsigned mask = __match_any_sync(0xffffffffu, bin);
        int rank = __popc(mask & ((1u << lane) - 1u));
        s_bin [c*32 + lane] = (unsigned char)bin;
        s_rank[c*32 + lane] = (unsigned char)rank;
        if (rank == 0) cnt[c][bin] = (unsigned short)__popc(mask);
    }
    __syncthreads();

    // phase 2: per-bin exclusive prefix over chunks (thread = bin)
    if (tid < NBIN) {
        int sum = 0;
        for (int c = 0; c < NCHUNK; c++) {
            int v = cnt[c][tid];
            cnt[c][tid] = (unsigned short)sum;
            sum += v;
        }
        binTot[tid] = sum;
    }
    __syncthreads();

    // phase 3: exclusive prefix over bins
    if (tid == 0) {
        int s = 0;
        for (int bn = 0; bn < NBIN; bn++) { binStart_s[bn] = s; s += binTot[bn]; }
        binStart_s[NBIN] = s;
    }
    __syncthreads();

    // publish duplicated binStart
    for (int t = tid; t <= 2*NBIN; t += 512)
        g_binStart[b][t] = (t <= NBIN) ? binStart_s[t] : binStart_s[t-NBIN] + S_;

    // phase 4: deterministic scatter (write both copies)
    for (int i0 = tid; i0 < S_; i0 += 512) {
        int i = b*S_ + i0;
        int bin = s_bin[i0];
        int c = i0 >> 5;
        int pos = binStart_s[bin] + (int)cnt[c][bin] + (int)s_rank[i0];
        float2 kv = g_Kvec[i];
        float  sv = g_SV[i];
        int base = b*2*S_;
        g_SK [base + pos]      = kv;
        g_SK [base + pos + S_] = kv;
        g_SSV[base + pos]      = sv;
        g_SSV[base + pos + S_] = sv;
    }
}

// ---------------------------------------------------------------------------
// Kernel C: pruned softmax attention. One WARP per (query, head); lanes read
// consecutive angle-sorted keys (coalesced, L1-resident). Only keys inside
// the analytic window [psi - dmax, psi + dmax] are evaluated; excluded keys
// are provably < 2^-30 of the score sup. Window start rounded down to a
// 32-boundary (extra keys are legitimate terms -> free alignment).
// ---------------------------------------------------------------------------
__global__ void __launch_bounds__(256) attn_kernel()
{
    int w    = (blockIdx.x * 256 + threadIdx.x) >> 5;  // global warp id = qh
    int lane = threadIdx.x & 31;
    int q = w >> 1;
    int b = q >> 12;                                   // / S_

    float4 Q = g_QH[w];
    float p0 = Q.x, p1 = Q.y, nM = Q.z, psi = Q.w;
    float M = -nM;
    float arg = 1.f - WCUT / M;                        // M==0 -> -inf -> pi
    float dmax = acosf(fmaxf(arg, -1.f));

    int lo0 = (int)floorf((psi - dmax) * INVBIN);
    int hi0 = (int)floorf((psi + dmax) * INVBIN);
    int span = hi0 - lo0;
    int lo = lo0;
    if (lo < 0) lo += NBIN;

    const int* bs = g_binStart[b];
    int s0 = bs[lo];
    int s1 = (span >= NBIN) ? (s0 + S_) : bs[lo + span + 1];
    s0 &= ~31;                                          // align (over-include)

    int base = b*2*S_;
    float den = 0.f, num = 0.f;
    for (int j = s0 + lane; j < s1; j += 32) {
        float2 kv = g_SK[base + j];
        float  sv = g_SSV[base + j];
        float s2 = fmaf(p0, kv.x, fmaf(p1, kv.y, nM)); // score - M <= 0
        float e;
        asm("ex2.approx.ftz.f32 %0, %1;" : "=f"(e) : "f"(s2));
        den += e;
        num = fmaf(e, sv, num);
    }
#pragma unroll
    for (int o = 16; o; o >>= 1) {
        den += __shfl_xor_sync(0xffffffffu, den, o);
        num += __shfl_xor_sync(0xffffffffu, num, o);
    }
    if (lane == 0) g_R[w] = num / den;
}

// ---------------------------------------------------------------------------
// Kernel D: rank-1 epilogue.
// ---------------------------------------------------------------------------
__global__ void __launch_bounds__(256) final_kernel(
    const float* __restrict__ ov, const float* __restrict__ uv,
    const float* __restrict__ ou, float* __restrict__ out)
{
    int i = blockIdx.x * blockDim.x + threadIdx.x;
    if (i >= NT) return;
    float r0 = g_R[i*2 + 0];
    float r1 = g_R[i*2 + 1];
    float C0 = uv[0]*ov[0] + uv[1]*ov[1];
    float C1 = uv[0]*ov[2] + uv[1]*ov[3];
    float so = r0*C0 + r1*C1;
    float* o = out + i * 5;
#pragma unroll
    for (int j = 0; j < 5; j++) o[j] = so * ou[j];
}

extern "C" void kernel_launch(void* const* d_in, const int* in_sizes, int n_in,
                              void* d_out, int out_size)
{
    const float* x     = (const float*)d_in[0];
    const float* freqs = (const float*)d_in[1];
    const float* qkv   = (const float*)d_in[2];
    const float* vv    = (const float*)d_in[3];
    const float* ov    = (const float*)d_in[4];
    const float* uv    = (const float*)d_in[5];
    const float* qu    = (const float*)d_in[6];
    const float* ku    = (const float*)d_in[7];
    const float* ou    = (const float*)d_in[8];

    prep_kernel<<<NT/128, 128>>>(x, freqs, qkv, vv, qu, ku);
    bin_kernel<<<B_, 512>>>();
    attn_kernel<<<(NT*H_*32)/256, 256>>>();
    final_kernel<<<NT/256, 256>>>(ov, uv, ou, (float*)d_out);
}